// round 11
// baseline (speedup 1.0000x reference)
#include <cuda_runtime.h>

#define N   1024
#define T   1024
#define NW  32
#define RCAP 30000

__device__ float g_dist[N * N];   // g_dist[j*N + i] = ||gen_j - gt_i|| (exact fp32)

// Order-preserving float -> uint32 mapping (exact, bijective, monotone).
__device__ __forceinline__ unsigned fkey(float f) {
    unsigned k = __float_as_uint(f);
    return (k & 0x80000000u) ? ~k : (k | 0x80000000u);
}
__device__ __forceinline__ float funkey(unsigned k) {
    unsigned b = (k & 0x80000000u) ? (k & 0x7fffffffu) : ~k;
    return __uint_as_float(b);
}

// ---- full-chip distance matrix precompute (amortized, exact sqrtf) ----
__global__ void dist_kernel(const float* __restrict__ gt,
                            const float* __restrict__ gen) {
    const int id = blockIdx.x * blockDim.x + threadIdx.x;   // 0 .. N*N-1
    const int j = id >> 10, i = id & (N - 1);
    const float dx = gen[3 * j]     - gt[3 * i];
    const float dy = gen[3 * j + 1] - gt[3 * i + 1];
    const float dz = gen[3 * j + 2] - gt[3 * i + 2];
    g_dist[id] = sqrtf(fmaf(dx, dx, fmaf(dy, dy, dz * dz)));
}

// Gauss-Seidel-ish auction (<=32 bidders/round, one per warp) with
// eps-scaling AND assignment keeping across phases (eps-CS audit).
// Bids via packed atomicMax (order-independent => deterministic).
__global__ __launch_bounds__(T, 1)
void emd_auction_kernel(float* __restrict__ out) {
    __shared__ __align__(16) float s_price[N];
    __shared__ unsigned long long s_slot[N];          // (fkey(pnew)<<32 | bidder)
    __shared__ short  s_owner[N];                     // object -> bidder (-1 free)
    __shared__ short  s_objof[N];                     // bidder -> object (-1 free)
    __shared__ unsigned short s_q[N];                 // unassigned bidders (sorted)
    __shared__ int    s_wcnt[NW], s_wpre[NW];
    __shared__ int    s_nq;
    __shared__ float  s_sum[NW];

    const int t = threadIdx.x, lane = t & 31, wid = t >> 5;

    s_price[t] = 0.0f;
    s_slot[t]  = 0ull;
    s_objof[t] = -1;
    s_owner[t] = -1;
    __syncthreads();

    float eps = 0.5f;
    int rounds = 0;                                   // uniform across threads

    for (int phase = 0; phase < 8; ++phase) {
        // ---- eps-CS audit: unassign only pairs violating the new eps ----
        if (phase > 0) {
            for (int b = wid; b < N; b += NW) {
                const int ij = s_objof[b];
                if (ij >= 0) {
                    const float4* drow = (const float4*)(g_dist + b * N);
                    const float4* prow = (const float4*)s_price;
                    float m1 = 3.0e38f;
                    #pragma unroll
                    for (int k = 0; k < 8; ++k) {
                        const int q = k * 32 + lane;
                        const float4 d = drow[q], p = prow[q];
                        m1 = fminf(m1, fminf(fminf(d.x + p.x, d.y + p.y),
                                             fminf(d.z + p.z, d.w + p.w)));
                    }
                    const unsigned mk = __reduce_min_sync(~0u, fkey(m1));
                    if (lane == 0) {
                        const float cj = g_dist[b * N + ij] + s_price[ij];
                        if (cj > funkey(mk) + eps) {    // violates new eps-CS
                            s_objof[b]  = -1;
                            s_owner[ij] = -1;
                        }
                    }
                }
            }
        }
        __syncthreads();

        // ---- build unassigned queue (index order => deterministic) ----
        {
            const bool un = (s_objof[t] < 0);
            const unsigned bal = __ballot_sync(~0u, un);
            if (lane == 0) s_wcnt[wid] = __popc(bal);
            __syncthreads();
            if (wid == 0) {
                const int c = s_wcnt[lane];
                int inc = c;
                #pragma unroll
                for (int o = 1; o < 32; o <<= 1) {
                    const int vv = __shfl_up_sync(~0u, inc, o);
                    if (lane >= o) inc += vv;
                }
                s_wpre[lane] = inc - c;
                if (lane == 31) s_nq = inc;
            }
            __syncthreads();
            if (un)
                s_q[s_wpre[wid] + __popc(bal & ((1u << lane) - 1u))] =
                    (unsigned short)t;
            __syncthreads();
        }

        while (s_nq > 0 && rounds < RCAP) {
            ++rounds;
            const int nb = min(s_nq, NW);

            // ---- bidding: warp w = bidder s_q[w] (fresh prices) ----
            if (wid < nb) {
                const int j = s_q[wid];
                const float4* drow = (const float4*)(g_dist + j * N);
                const float4* prow = (const float4*)s_price;
                float m1a = 3.0e38f, m2a = 3.0e38f; int i1a = 0;
                float m1b = 3.0e38f, m2b = 3.0e38f; int i1b = 0;
                #pragma unroll
                for (int k = 0; k < 8; k += 2) {
                    {
                        const int q = k * 32 + lane;
                        const float4 d = drow[q], p = prow[q];
                        const int ib = q << 2;
                        float c;
                        c = d.x + p.x; if (c < m1a) { m2a = m1a; m1a = c; i1a = ib;     } else if (c < m2a) m2a = c;
                        c = d.y + p.y; if (c < m1a) { m2a = m1a; m1a = c; i1a = ib + 1; } else if (c < m2a) m2a = c;
                        c = d.z + p.z; if (c < m1a) { m2a = m1a; m1a = c; i1a = ib + 2; } else if (c < m2a) m2a = c;
                        c = d.w + p.w; if (c < m1a) { m2a = m1a; m1a = c; i1a = ib + 3; } else if (c < m2a) m2a = c;
                    }
                    {
                        const int q = (k + 1) * 32 + lane;
                        const float4 d = drow[q], p = prow[q];
                        const int ib = q << 2;
                        float c;
                        c = d.x + p.x; if (c < m1b) { m2b = m1b; m1b = c; i1b = ib;     } else if (c < m2b) m2b = c;
                        c = d.y + p.y; if (c < m1b) { m2b = m1b; m1b = c; i1b = ib + 1; } else if (c < m2b) m2b = c;
                        c = d.z + p.z; if (c < m1b) { m2b = m1b; m1b = c; i1b = ib + 2; } else if (c < m2b) m2b = c;
                        c = d.w + p.w; if (c < m1b) { m2b = m1b; m1b = c; i1b = ib + 3; } else if (c < m2b) m2b = c;
                    }
                }
                float m1, m2; int i1;
                if (m1a <= m1b) { m1 = m1a; i1 = i1a; m2 = fminf(m2a, m1b); }
                else            { m1 = m1b; i1 = i1b; m2 = fminf(m2b, m1a); }
                #pragma unroll
                for (int o = 16; o; o >>= 1) {      // warp top-2 reduce
                    const float om1 = __shfl_xor_sync(~0u, m1, o);
                    const float om2 = __shfl_xor_sync(~0u, m2, o);
                    const int   oi1 = __shfl_xor_sync(~0u, i1, o);
                    if (om1 < m1) { m2 = fminf(m1, om2); m1 = om1; i1 = oi1; }
                    else          { m2 = fminf(m2, om1); }
                }
                if (lane == 0) {
                    const float pnew = s_price[i1] + (m2 - m1) + eps;
                    atomicMax(&s_slot[i1],
                              ((unsigned long long)fkey(pnew) << 32) | (unsigned)j);
                }
            }
            __syncthreads();

            // ---- resolve: one object per thread ----
            {
                const unsigned long long s = s_slot[t];
                if (s) {
                    const int j = (int)(s & 0xffffffffu);
                    const int prev = s_owner[t];
                    if (prev >= 0) s_objof[prev] = -1;
                    s_owner[t] = (short)j;
                    s_objof[j] = (short)t;
                    s_price[t] = funkey((unsigned)(s >> 32));
                    s_slot[t] = 0ull;
                }
            }
            __syncthreads();

            // ---- rebuild unassigned queue (index order => deterministic) ----
            const bool un = (s_objof[t] < 0);
            const unsigned bal = __ballot_sync(~0u, un);
            if (lane == 0) s_wcnt[wid] = __popc(bal);
            __syncthreads();
            if (wid == 0) {
                const int c = s_wcnt[lane];
                int inc = c;
                #pragma unroll
                for (int o = 1; o < 32; o <<= 1) {
                    const int vv = __shfl_up_sync(~0u, inc, o);
                    if (lane >= o) inc += vv;
                }
                s_wpre[lane] = inc - c;
                if (lane == 31) s_nq = inc;
            }
            __syncthreads();
            if (un)
                s_q[s_wpre[wid] + __popc(bal & ((1u << lane) - 1u))] =
                    (unsigned short)t;
            __syncthreads();
        }
        eps *= 0.25f;
    }

    // deterministic greedy completion (only if round cap hit; normally no-op)
    if (t == 0 && s_nq > 0) {
        for (int j = 0; j < N; ++j) if (s_objof[j] < 0) {
            for (int i = 0; i < N; ++i) if (s_owner[i] < 0) {
                s_owner[i] = (short)j; s_objof[j] = (short)i; break;
            }
        }
    }
    __syncthreads();

    // ---- exact mean of matched distances (precomputed exact fp32) ----
    float acc = g_dist[t * N + (int)s_objof[t]];
    #pragma unroll
    for (int o2 = 16; o2; o2 >>= 1) acc += __shfl_down_sync(~0u, acc, o2);
    if (lane == 0) s_sum[wid] = acc;
    __syncthreads();
    if (t == 0) {
        float s = 0.0f;
        #pragma unroll
        for (int w = 0; w < NW; ++w) s += s_sum[w];
        out[0] = s * (1.0f / (float)N);
    }
}

extern "C" void kernel_launch(void* const* d_in, const int* in_sizes, int n_in,
                              void* d_out, int out_size) {
    const float* gt  = (const float*)d_in[0];   // (1,1024,3) fp32
    const float* gen = (const float*)d_in[1];   // (1,1024,3) fp32
    (void)in_sizes; (void)n_in; (void)out_size;
    dist_kernel<<<(N * N) / 256, 256>>>(gt, gen);
    emd_auction_kernel<<<1, T>>>((float*)d_out);
}

// round 12
// speedup vs baseline: 2.3831x; 2.3831x over previous
#include <cuda_runtime.h>

#define N   1024
#define T   1024
#define NW  32
#define RCAP 30000

__device__ float    g_dist[N * N];   // exact fp32 distances (final mean)
__device__ unsigned g_mat[N * N];    // (d20 << 10) | col_index
__device__ unsigned g_dmax = 0;      // bits of max distance (positive floats)

// ---- pass 1: exact distances + global max (atomicMax, order-independent) ----
__global__ void dist_kernel(const float* __restrict__ gt,
                            const float* __restrict__ gen) {
    const int id = blockIdx.x * blockDim.x + threadIdx.x;
    const int j = id >> 10, i = id & (N - 1);
    const float dx = gen[3 * j]     - gt[3 * i];
    const float dy = gen[3 * j + 1] - gt[3 * i + 1];
    const float dz = gen[3 * j + 2] - gt[3 * i + 2];
    const float d = sqrtf(fmaf(dx, dx, fmaf(dy, dy, dz * dz)));
    g_dist[id] = d;
    atomicMax(&g_dmax, __float_as_uint(d));   // d >= 0: uint order == float order
}

// ---- pass 2: quantize to 20 bits, pack column index in low 10 bits ----
__global__ void quant_kernel() {
    const int id = blockIdx.x * blockDim.x + threadIdx.x;
    const float dmax = __uint_as_float(g_dmax);
    const float scale = 1048000.0f / dmax;
    const unsigned dq = __float2uint_rn(g_dist[id] * scale);   // <= 1048000
    g_mat[id] = (dq << 10) | (unsigned)(id & (N - 1));
}

// Auction with integer eps-scaling (R9 structure: <=32 fresh-price bidders
// per round, full restart per phase). Scan = IADD + branch-free integer
// top-2 on packed keys; bids via u64 atomicMax (order-independent).
__global__ __launch_bounds__(T, 1)
void emd_auction_kernel(float* __restrict__ out) {
    __shared__ __align__(16) unsigned s_pshift[N];    // price << 10
    __shared__ unsigned long long s_slot[N];          // (pnew<<32 | bidder)
    __shared__ short  s_owner[N];                     // object -> bidder (-1 free)
    __shared__ short  s_objof[N];                     // bidder -> object (-1 free)
    __shared__ unsigned short s_q[N];                 // unassigned bidders (sorted)
    __shared__ int    s_wcnt[NW], s_wpre[NW];
    __shared__ int    s_nq;
    __shared__ float  s_sum[NW];

    const int t = threadIdx.x, lane = t & 31, wid = t >> 5;

    s_pshift[t] = 0u;
    s_slot[t]   = 0ull;
    s_objof[t]  = -1;
    s_owner[t]  = -1;
    __syncthreads();

    int rounds = 0;
    unsigned eps = 49152u;                            // /4 per phase -> 3

    for (int phase = 0; phase < 8; ++phase) {
        // reset assignment, keep prices
        s_owner[t] = -1; s_objof[t] = -1;
        s_q[t] = (unsigned short)t;
        if (t == 0) s_nq = N;
        __syncthreads();

        while (s_nq > 0 && rounds < RCAP) {
            ++rounds;
            const int nb = min(s_nq, NW);

            // ---- bidding: warp w = bidder s_q[w] (fresh prices) ----
            if (wid < nb) {
                const int j = s_q[wid];
                const uint4* mrow = (const uint4*)(g_mat + j * N);
                const uint4* prow = (const uint4*)s_pshift;
                unsigned m1 = 0xffffffffu, m2 = 0xffffffffu;
                #pragma unroll
                for (int k = 0; k < 8; ++k) {
                    const int q = k * 32 + lane;
                    const uint4 d = mrow[q];
                    const uint4 p = prow[q];
                    unsigned kk, tt;
                    kk = d.x + p.x; tt = max(m1, kk); m1 = min(m1, kk); m2 = min(m2, tt);
                    kk = d.y + p.y; tt = max(m1, kk); m1 = min(m1, kk); m2 = min(m2, tt);
                    kk = d.z + p.z; tt = max(m1, kk); m1 = min(m1, kk); m2 = min(m2, tt);
                    kk = d.w + p.w; tt = max(m1, kk); m1 = min(m1, kk); m2 = min(m2, tt);
                }
                #pragma unroll
                for (int o = 16; o; o >>= 1) {        // warp top-2 reduce
                    const unsigned om1 = __shfl_xor_sync(~0u, m1, o);
                    const unsigned om2 = __shfl_xor_sync(~0u, m2, o);
                    const unsigned tt  = max(m1, om1);
                    m1 = min(m1, om1);
                    m2 = min(m2, min(om2, tt));
                }
                if (lane == 0) {
                    const unsigned i1 = m1 & 1023u;
                    const unsigned c1 = m1 >> 10, c2 = m2 >> 10;
                    const unsigned p1 = s_pshift[i1] >> 10;
                    const unsigned long long pnew = (unsigned long long)
                        min(p1 + (c2 - c1) + eps, 4190000u);
                    atomicMax(&s_slot[i1], (pnew << 32) | (unsigned)j);
                }
            }
            __syncthreads();

            // ---- resolve: one object per thread ----
            {
                const unsigned long long s = s_slot[t];
                if (s) {
                    const int j = (int)(s & 0xffffffffull);
                    const int prev = s_owner[t];
                    if (prev >= 0) s_objof[prev] = -1;
                    s_owner[t] = (short)j;
                    s_objof[j] = (short)t;
                    s_pshift[t] = ((unsigned)(s >> 32)) << 10;
                    s_slot[t] = 0ull;
                }
            }
            __syncthreads();

            // ---- rebuild unassigned queue (index order => deterministic) ----
            const bool un = (s_objof[t] < 0);
            const unsigned bal = __ballot_sync(~0u, un);
            if (lane == 0) s_wcnt[wid] = __popc(bal);
            __syncthreads();
            if (wid == 0) {
                const int c = s_wcnt[lane];
                int inc = c;
                #pragma unroll
                for (int o = 1; o < 32; o <<= 1) {
                    const int vv = __shfl_up_sync(~0u, inc, o);
                    if (lane >= o) inc += vv;
                }
                s_wpre[lane] = inc - c;
                if (lane == 31) s_nq = inc;
            }
            __syncthreads();
            if (un)
                s_q[s_wpre[wid] + __popc(bal & ((1u << lane) - 1u))] =
                    (unsigned short)t;
            __syncthreads();
        }
        eps >>= 2;
    }

    // deterministic greedy completion (only if round cap hit; normally no-op)
    if (t == 0 && s_nq > 0) {
        for (int j = 0; j < N; ++j) if (s_objof[j] < 0) {
            for (int i = 0; i < N; ++i) if (s_owner[i] < 0) {
                s_owner[i] = (short)j; s_objof[j] = (short)i; break;
            }
        }
    }
    __syncthreads();

    // ---- exact mean of matched distances (fp32 matrix) ----
    float acc = g_dist[t * N + (int)s_objof[t]];
    #pragma unroll
    for (int o2 = 16; o2; o2 >>= 1) acc += __shfl_down_sync(~0u, acc, o2);
    if (lane == 0) s_sum[wid] = acc;
    __syncthreads();
    if (t == 0) {
        float s = 0.0f;
        #pragma unroll
        for (int w = 0; w < NW; ++w) s += s_sum[w];
        out[0] = s * (1.0f / (float)N);
    }
}

extern "C" void kernel_launch(void* const* d_in, const int* in_sizes, int n_in,
                              void* d_out, int out_size) {
    const float* gt  = (const float*)d_in[0];   // (1,1024,3) fp32
    const float* gen = (const float*)d_in[1];   // (1,1024,3) fp32
    (void)in_sizes; (void)n_in; (void)out_size;
    dist_kernel<<<(N * N) / 256, 256>>>(gt, gen);
    quant_kernel<<<(N * N) / 256, 256>>>();
    emd_auction_kernel<<<1, T>>>((float*)d_out);
}